// round 9
// baseline (speedup 1.0000x reference)
#include <cuda_runtime.h>
#include <cstdint>

#define NN 50000
#define EE 800000
#define INF 128
#define HD  128
#define NEG 0.2f
#define LOG2E 1.44269504088896340736f

#define BM 128
#define NTILE ((NN + BM - 1) / BM)    // 391
#define HBLK 148                       // histogram blocks (bids 0..147)
#define SCANB HBLK                     // scan block (bid 148)
#define SCAT0 (SCANB + 1)              // scatter blocks (bids 149..295)
#define SBLK 147
#define GEMM0 (SCAT0 + SBLK)           // 296
#define NGEMM (3 * NTILE)              // 1173 (one matrix-tile per block)
#define GRID1 (GEMM0 + NGEMM)

#define WST 68                         // uint32 stride per W row: bank-bijective
#define SMEM_BYTES (2 * 128 * WST * 4) // hi + lo fragment tiles = 69632 B

// ---------------- scratch ------------------------------------------------------
__device__ float g_fsv [(size_t)NN * 256];  // [node][0:128)=f_src*LOG2E, [128:256)=f_v
__device__ float g_fdst[(size_t)NN * HD];   // pre-scaled by LOG2E
__device__ int   g_deg [NN];                // zeroed by scan pass each launch
__device__ int   g_offs[NN + 1];
__device__ int   g_cur [NN];
__device__ int   g_ssrc[EE];
__device__ int   g_histdone;
__device__ int   g_scandone;

__device__ __forceinline__ float ex2f(float x) {
    float r;
    asm("ex2.approx.f32 %0, %1;" : "=f"(r) : "f"(x));
    return r;
}

// pack two f32 into bf16x2 (lo -> low half, hi -> high half)
__device__ __forceinline__ uint32_t pack_bf16x2(float lo, float hi) {
    uint32_t u;
    asm("cvt.rn.bf16x2.f32 %0, %1, %2;" : "=r"(u) : "f"(hi), "f"(lo));
    return u;
}
__device__ __forceinline__ float bflo(uint32_t u) { return __uint_as_float(u << 16); }
__device__ __forceinline__ float bfhi(uint32_t u) { return __uint_as_float(u & 0xffff0000u); }

// split float2 -> (hi bf16x2, residual bf16x2)
__device__ __forceinline__ void split2(float2 v, uint32_t& h, uint32_t& l) {
    h = pack_bf16x2(v.x, v.y);
    l = pack_bf16x2(v.x - bflo(h), v.y - bfhi(h));
}

#define MMA16816(d, a, b0, b1)                                                    \
    asm volatile("mma.sync.aligned.m16n8k16.row.col.f32.bf16.bf16.f32 "           \
                 "{%0,%1,%2,%3}, {%4,%5,%6,%7}, {%8,%9}, {%0,%1,%2,%3};"          \
                 : "+f"((d)[0]), "+f"((d)[1]), "+f"((d)[2]), "+f"((d)[3])         \
                 : "r"((a)[0]), "r"((a)[1]), "r"((a)[2]), "r"((a)[3]),            \
                   "r"(b0), "r"(b1))

// ---------------- mega-kernel: hist+scan+scatter (wave 1) + HMMA GEMM ----------
__global__ void __launch_bounds__(256, 2)
gemm_csr_kernel(const float* __restrict__ feat,
                const float* __restrict__ Wsrc, const float* __restrict__ bsrc,
                const float* __restrict__ Wdst, const float* __restrict__ bdst,
                const float* __restrict__ Wv,   const float* __restrict__ bv,
                const int* __restrict__ src, const int* __restrict__ dst)
{
    const int bid = blockIdx.x;
    const int tid = threadIdx.x;

    // ---------- role: histogram ----------
    if (bid < HBLK) {
        for (int i = bid * 256 + tid; i < EE; i += HBLK * 256)
            atomicAdd(&g_deg[dst[i]], 1);
        __threadfence();
        __syncthreads();
        if (tid == 0) atomicAdd(&g_histdone, 1);
        return;
    }

    // ---------- role: scan (single block; spins until hist done) ----------
    if (bid == SCANB) {
        if (tid == 0) {
            while (atomicAdd(&g_histdone, 0) < HBLK) __nanosleep(128);
            atomicExch(&g_histdone, 0);
        }
        __syncthreads();
        __threadfence();

        const int CH = (NN + 255) / 256;
        const int beg = tid * CH;
        const int end = (beg + CH < NN) ? beg + CH : NN;

        int s = 0;
#pragma unroll 4
        for (int i = beg; i < end; i++) s += __ldcg(&g_deg[i]);

        __shared__ int wsum[8];
        const int lane = tid & 31, wid = tid >> 5;
        int inc = s;
#pragma unroll
        for (int o = 1; o < 32; o <<= 1) {
            const int u = __shfl_up_sync(0xffffffffu, inc, o);
            if (lane >= o) inc += u;
        }
        if (lane == 31) wsum[wid] = inc;
        __syncthreads();
        if (wid == 0 && lane < 8) {
            int w = wsum[lane];
#pragma unroll
            for (int o = 1; o < 8; o <<= 1) {
                const int u = __shfl_up_sync(0x000000ffu, w, o);
                if (lane >= o) w += u;
            }
            wsum[lane] = w;
        }
        __syncthreads();
        int run = (inc - s) + (wid ? wsum[wid - 1] : 0);

#pragma unroll 4
        for (int i = beg; i < end; i++) {
            const int d = __ldcg(&g_deg[i]);
            __stcg(&g_deg[i], 0);
            g_offs[i] = run;
            g_cur[i]  = run;
            run += d;
        }
        if (tid == 255) g_offs[NN] = run;

        __threadfence();
        __syncthreads();
        if (tid == 0) atomicExch(&g_scandone, 1);
        return;
    }

    // ---------- role: scatter (spins until scan done) ----------
    if (bid < GEMM0) {
        if (tid == 0)
            while (atomicAdd(&g_scandone, 0) == 0) __nanosleep(128);
        __syncthreads();
        for (int i = (bid - SCAT0) * 256 + tid; i < EE; i += SBLK * 256) {
            const int d = dst[i];
            const int p = atomicAdd(&g_cur[d], 1);
            g_ssrc[p] = src[i];
        }
        return;
    }

    // ---------- role: HMMA GEMM (bf16-split; W pre-split into smem once) ----
    extern __shared__ uint32_t wsm[];
    uint32_t* Whs = wsm;               // [128][WST] hi fragments (bf16x2 k-pairs)
    uint32_t* Wls = wsm + 128 * WST;   // [128][WST] lo (residual) fragments

    const int bx   = bid - GEMM0;
    const int mat  = bx / NTILE;
    const int tile = bx % NTILE;
    const int m0g  = tile * BM;

    const float* W;
    const float* b;
    float* Out;
    float scale;
    unsigned rstride;
    if (mat == 0)      { W = Wsrc; b = bsrc; Out = g_fsv;       scale = LOG2E; rstride = 256; }
    else if (mat == 1) { W = Wdst; b = bdst; Out = g_fdst;      scale = LOG2E; rstride = 128; }
    else               { W = Wv;   b = bv;   Out = g_fsv + 128; scale = 1.0f;  rstride = 256; }

    // --- cooperative W convert: row = tid/2, half = tid&1 (32 k-pairs each) ---
    {
        const int rw = tid >> 1, hf = tid & 1;
        const float* wr = W + (size_t)rw * INF + hf * 64;
        uint32_t* dh = Whs + rw * WST + hf * 32;
        uint32_t* dl = Wls + rw * WST + hf * 32;
#pragma unroll 8
        for (int i = 0; i < 32; i++) {
            const float2 v = *(const float2*)(wr + 2 * i);
            uint32_t h, l;
            split2(v, h, l);
            dh[i] = h;
            dl[i] = l;
        }
    }
    __syncthreads();

    const int wm   = tid >> 5;          // warp's m-group
    const int lane = tid & 31;
    const int gi   = lane >> 2;         // group id 0..7
    const int tg   = lane & 3;          // thread-in-group

    const int r0 = m0g + wm * 16 + gi;  // fragment row (lo)
    const int r1 = r0 + 8;              // fragment row (hi)
    const bool v0 = (r0 < NN);
    const bool v1 = (r1 < NN);
    const int kcol = tg * 2;

    float acc[16][4];
#pragma unroll
    for (int ng = 0; ng < 16; ng++)
#pragma unroll
        for (int i = 0; i < 4; i++) acc[ng][i] = 0.f;

    const float* a0p = feat + (size_t)r0 * INF + kcol;
    const float* a1p = feat + (size_t)r1 * INF + kcol;

#pragma unroll
    for (int kg = 0; kg < 8; kg++) {
        const int kb = kg * 16;
        // ---- A fragments (hi/lo split) ----
        float2 fa0 = v0 ? *(const float2*)(a0p + kb)     : make_float2(0.f, 0.f);
        float2 fa1 = v1 ? *(const float2*)(a1p + kb)     : make_float2(0.f, 0.f);
        float2 fa2 = v0 ? *(const float2*)(a0p + kb + 8) : make_float2(0.f, 0.f);
        float2 fa3 = v1 ? *(const float2*)(a1p + kb + 8) : make_float2(0.f, 0.f);
        uint32_t ah[4], al[4];
        split2(fa0, ah[0], al[0]);
        split2(fa1, ah[1], al[1]);
        split2(fa2, ah[2], al[2]);
        split2(fa3, ah[3], al[3]);

        const uint32_t kidx = kg * 8 + tg;
#pragma unroll
        for (int ng = 0; ng < 16; ng++) {
            const uint32_t base = (uint32_t)(ng * 8 + gi) * WST + kidx;
            const uint32_t bh0 = Whs[base];
            const uint32_t bh1 = Whs[base + 4];
            const uint32_t bl0 = Wls[base];
            const uint32_t bl1 = Wls[base + 4];
            MMA16816(acc[ng], ah, bh0, bh1);
            MMA16816(acc[ng], al, bh0, bh1);
            MMA16816(acc[ng], ah, bl0, bl1);
        }
    }

    // ---- epilogue: bias + scale, direct float2 stores ----
#pragma unroll
    for (int ng = 0; ng < 16; ng++) {
        const int c = ng * 8 + kcol;
        const float2 bb = *(const float2*)(b + c);
        if (v0) {
            float2 o;
            o.x = (acc[ng][0] + bb.x) * scale;
            o.y = (acc[ng][1] + bb.y) * scale;
            *(float2*)(Out + (size_t)r0 * rstride + c) = o;
        }
        if (v1) {
            float2 o;
            o.x = (acc[ng][2] + bb.x) * scale;
            o.y = (acc[ng][3] + bb.y) * scale;
            *(float2*)(Out + (size_t)r1 * rstride + c) = o;
        }
    }
}

// ---------------- aggregation: one warp per dst node --------------------------
__global__ void aggregate_kernel(float* __restrict__ out)
{
    if (blockIdx.x == 0 && threadIdx.x == 0) atomicExch(&g_scandone, 0);

    const int warp = (blockIdx.x * blockDim.x + threadIdx.x) >> 5;
    if (warp >= NN) return;
    const int lane = threadIdx.x & 31;
    const unsigned lane4 = lane * 4;
    const int n = warp;

    const int beg = g_offs[n];
    const int end = g_offs[n + 1];

    const unsigned fo = ((unsigned)n << 7) + lane4;
    const float4 fd = *(const float4*)(g_fdst + fo);

    float nx = 0.f, ny = 0.f, nz = 0.f, nw = 0.f;
    float dx = 0.f, dy = 0.f, dz = 0.f, dw = 0.f;

#define EDGE_STEP(fs, fvv)                                                        \
    do {                                                                          \
        float a_, e_;                                                             \
        a_ = fs.x + fd.x; e_ = ex2f(fmaxf(a_, NEG * a_)); dx += e_; nx = fmaf(fvv.x, e_, nx); \
        a_ = fs.y + fd.y; e_ = ex2f(fmaxf(a_, NEG * a_)); dy += e_; ny = fmaf(fvv.y, e_, ny); \
        a_ = fs.z + fd.z; e_ = ex2f(fmaxf(a_, NEG * a_)); dz += e_; nz = fmaf(fvv.z, e_, nz); \
        a_ = fs.w + fd.w; e_ = ex2f(fmaxf(a_, NEG * a_)); dw += e_; nw = fmaf(fvv.w, e_, nw); \
    } while (0)

    for (int base = beg; base < end; base += 32) {
        const int rem = end - base;
        const int m = rem < 32 ? rem : 32;
        const int s_l = (lane < m) ? __ldg(&g_ssrc[base + lane]) : 0;
        int t = 0;
        for (; t + 2 <= m; t += 2) {
            const unsigned o0 = ((unsigned)__shfl_sync(0xffffffffu, s_l, t)     << 8) + lane4;
            const unsigned o1 = ((unsigned)__shfl_sync(0xffffffffu, s_l, t + 1) << 8) + lane4;
            const float4 fs0 = *(const float4*)(g_fsv + o0);
            const float4 fv0 = *(const float4*)(g_fsv + o0 + 128);
            const float4 fs1 = *(const float4*)(g_fsv + o1);
            const float4 fv1 = *(const float4*)(g_fsv + o1 + 128);
            EDGE_STEP(fs0, fv0);
            EDGE_STEP(fs1, fv1);
        }
        if (t < m) {
            const unsigned o0 = ((unsigned)__shfl_sync(0xffffffffu, s_l, t) << 8) + lane4;
            const float4 fs0 = *(const float4*)(g_fsv + o0);
            const float4 fv0 = *(const float4*)(g_fsv + o0 + 128);
            EDGE_STEP(fs0, fv0);
        }
    }

    float4 o;
    o.x = dx > 0.f ? nx / dx : 0.f;
    o.y = dy > 0.f ? ny / dy : 0.f;
    o.z = dz > 0.f ? nz / dz : 0.f;
    o.w = dw > 0.f ? nw / dw : 0.f;
    *(float4*)(out + fo) = o;
}

// ---------------- launch -------------------------------------------------------
extern "C" void kernel_launch(void* const* d_in, const int* in_sizes, int n_in,
                              void* d_out, int out_size)
{
    const float* feat = (const float*)d_in[0];
    const float* Wsrc = (const float*)d_in[1];
    const float* bsrc = (const float*)d_in[2];
    const float* Wdst = (const float*)d_in[3];
    const float* bdst = (const float*)d_in[4];
    const float* Wv   = (const float*)d_in[5];
    const float* bv   = (const float*)d_in[6];
    const int*   src  = (const int*)d_in[7];
    const int*   dst  = (const int*)d_in[8];
    float* out = (float*)d_out;

    cudaFuncSetAttribute(gemm_csr_kernel,
                         cudaFuncAttributeMaxDynamicSharedMemorySize, SMEM_BYTES);

    gemm_csr_kernel<<<GRID1, 256, SMEM_BYTES>>>(
        feat, Wsrc, bsrc, Wdst, bdst, Wv, bv, src, dst);

    aggregate_kernel<<<(NN * 32 + 255) / 256, 256>>>(out);
}